// round 15
// baseline (speedup 1.0000x reference)
#include <cuda_runtime.h>
#include <cuda_fp16.h>
#include <cstdint>

#define B   64
#define H   480
#define W   640
#define PH  64
#define PW  512
#define FS  15
#define NF  7
#define RAD 7

#define K_TOT   (PH*PW)          // 32768
#define N_ROWS  (B*NF)           // 448

#define CODES_OFF 0
#define GRAM_OFF  (B*NF*PH*PW)                // 14680064
#define POLAR_OFF (GRAM_OFF + N_ROWS*N_ROWS)  // 14880768

#define FSCALE      0.0625f                   // feats stored * 1/16
#define GRAM_SCALE  (256.0f / 14680064.0f)    // undo FSCALE^2 and normalize

// ---- gram tiling ----
// 1024 total k-iterations (KB=32) split unevenly over 29 CTAs per pair:
// splits 0..8 do 36 iters, 9..28 do 35  (9*36 + 20*35 = 1024).
// Grid = 10 x 29 = 290 CTAs = ONE wave at 2 CTAs/SM on 148 SMs.
#define GT       4
#define GPAIRS   10
#define GKSPLIT  29
#define KB       32

#define TSTRIDE  40                 // fp16 per smem row (80B)
#define TILE_BY  (128*TSTRIDE*2)    // 10240 B
#define STAGE_BY (2*TILE_BY)        // 20480 B (A|B, single term)
#define NSTAGE   4
#define GSMEM    (NSTAGE*STAGE_BY)  // 81920 B -> 2 CTAs/SM

// ---- conv (fp16 implicit GEMM, single term) ----
#define SAB 536                     // fp16 stride per A row
#define SAU 268                     // u32 stride
#define AROWS 22                    // 8 + 14
#define ATILE_U32 (AROWS*SAU)       // 5896
#define CONV_SMEM ((2*ATILE_U32 + 960)*4)     // 51008 B -> 4 CTAs/SM

// scratch (device-code references ONLY — host-side symbol use is a silent
// ATS write to host BSS on GB300)
__device__ __half g_h[(size_t)N_ROWS * K_TOT];
__device__ float g_gpart[GPAIRS][GKSPLIT][128*128];

// ===========================================================================
// helpers
// ===========================================================================
__device__ __forceinline__ uint32_t smem_u32(const void* p) {
    uint32_t a;
    asm("{ .reg .u64 t; cvta.to.shared.u64 t, %1; cvt.u32.u64 %0, t; }" : "=r"(a) : "l"(p));
    return a;
}

__device__ __forceinline__ void cp16(uint32_t dst, const void* src) {
    asm volatile("cp.async.ca.shared.global [%0], [%1], 16;" :: "r"(dst), "l"(src));
}
__device__ __forceinline__ void cp16z(uint32_t dst, const void* src) {
    asm volatile("cp.async.ca.shared.global [%0], [%1], 16, 0;" :: "r"(dst), "l"(src));
}
__device__ __forceinline__ void cp_commit() { asm volatile("cp.async.commit_group;" ::: "memory"); }
__device__ __forceinline__ void cp_wait2()  { asm volatile("cp.async.wait_group 2;" ::: "memory"); }

__device__ __forceinline__ void ldm_x4(uint32_t* r, uint32_t addr) {
    asm volatile("ldmatrix.sync.aligned.m8n8.x4.shared.b16 {%0,%1,%2,%3}, [%4];"
        : "=r"(r[0]), "=r"(r[1]), "=r"(r[2]), "=r"(r[3]) : "r"(addr));
}
__device__ __forceinline__ void mma_f16(float* c, const uint32_t* a, uint32_t b0, uint32_t b1) {
    asm volatile("mma.sync.aligned.m16n8k16.row.col.f32.f16.f16.f32 "
        "{%0,%1,%2,%3}, {%4,%5,%6,%7}, {%8,%9}, {%0,%1,%2,%3};"
        : "+f"(c[0]), "+f"(c[1]), "+f"(c[2]), "+f"(c[3])
        : "r"(a[0]), "r"(a[1]), "r"(a[2]), "r"(a[3]), "r"(b0), "r"(b1));
}

// ===========================================================================
// Kernel 1: polar bilinear resample (MUFU sin/cos)
// ===========================================================================
__global__ void polar_kernel(const float* __restrict__ img,
                             const float* __restrict__ pupil,
                             const float* __restrict__ iris,
                             float* __restrict__ polar) {
    int idx = blockIdx.x * blockDim.x + threadIdx.x;
    if (idx >= B * PH * PW) return;
    int col = idx % PW;
    int row = (idx / PW) % PH;
    int b   = idx / (PH * PW);

    float theta = 6.283185307179586f * (float)(col + 1) * (1.0f / (float)PW);
    float ct = __cosf(theta), st = __sinf(theta);

    float pcx = pupil[b*3+0], pcy = pupil[b*3+1], pr = pupil[b*3+2];
    float icx = iris [b*3+0], icy = iris [b*3+1], ir = iris [b*3+2];

    float px = pcx + pr * ct;
    float py = pcy + pr * st;
    float ix = icx + ir * ct;
    float iy = icy + ir * st;

    float rad = (float)row / (float)(PH - 1);
    float xg = (1.0f - rad) * px + rad * ix;
    float yg = (1.0f - rad) * py + rad * iy;

    float x = fminf(fmaxf(xg, 0.0f), (float)(W - 1));
    float y = fminf(fmaxf(yg, 0.0f), (float)(H - 1));

    float xn = x / (float)(W - 1) * 2.0f - 1.0f;
    float yn = y / (float)(H - 1) * 2.0f - 1.0f;
    float gx = ((xn + 1.0f) * 0.5f * (float)W - 0.5f) / (float)(W - 1) * 2.0f - 1.0f;
    float gy = ((yn + 1.0f) * 0.5f * (float)H - 0.5f) / (float)(H - 1) * 2.0f - 1.0f;
    float sx = ((gx + 1.0f) * (float)W - 1.0f) * 0.5f;
    float sy = ((gy + 1.0f) * (float)H - 1.0f) * 0.5f;

    float x0f = floorf(sx), y0f = floorf(sy);
    float wx = sx - x0f, wy = sy - y0f;
    int x0 = (int)x0f, y0 = (int)y0f;

    const float* im = img + (size_t)b * H * W;

    float v00 = 0.f, v01 = 0.f, v10 = 0.f, v11 = 0.f;
    bool xv0 = (x0 >= 0) && (x0 < W);
    bool xv1 = (x0+1 >= 0) && (x0+1 < W);
    bool yv0 = (y0 >= 0) && (y0 < H);
    bool yv1 = (y0+1 >= 0) && (y0+1 < H);
    int x0c = min(max(x0, 0), W-1), x1c = min(max(x0+1, 0), W-1);
    int y0c = min(max(y0, 0), H-1), y1c = min(max(y0+1, 0), H-1);
    if (xv0 && yv0) v00 = im[y0c*W + x0c] * 255.0f;
    if (xv1 && yv0) v01 = im[y0c*W + x1c] * 255.0f;
    if (xv0 && yv1) v10 = im[y1c*W + x0c] * 255.0f;
    if (xv1 && yv1) v11 = im[y1c*W + x1c] * 255.0f;

    float v = v00*(1.0f-wx)*(1.0f-wy) + v01*wx*(1.0f-wy)
            + v10*(1.0f-wx)*wy        + v11*wx*wy;
    polar[idx] = v;
}

// ===========================================================================
// Kernel 2: conv as fp16 implicit GEMM, SINGLE term. (unchanged R10)
// ===========================================================================
__global__ __launch_bounds__(256, 4)
void conv_mma_kernel(const float* __restrict__ polar,
                     const float* __restrict__ filt,
                     float* __restrict__ codes) {
    extern __shared__ uint32_t cs[];
    uint32_t* aE  = cs;
    uint32_t* aO  = cs + ATILE_U32;
    uint32_t* Bs  = cs + 2*ATILE_U32;

    int b  = blockIdx.x;
    int y0 = blockIdx.y * 8;
    int tid = threadIdx.x, wid = tid >> 5, lane = tid & 31;

    for (int e = tid; e < 960; e += 256) {
        int i = e >> 6, kp = (e >> 3) & 7, n = e & 7;
        int k0 = 2*kp, k1 = 2*kp + 1;
        float w0 = (k0 < FS && n < NF) ? filt[(i*FS + k0)*NF + (6 - n)] : 0.f;
        float w1 = (k1 < FS && n < NF) ? filt[(i*FS + k1)*NF + (6 - n)] : 0.f;
        __half h0 = __float2half(w0);
        __half h1 = __float2half(w1);
        Bs[e] = ((uint32_t)__half_as_ushort(h1) << 16) | __half_as_ushort(h0);
    }
    const float* pb = polar + (size_t)b * PH * PW;
    __half* aEh = (__half*)aE;
    __half* aOh = (__half*)aO;
    for (int e = tid; e < AROWS * 529; e += 256) {
        int r = e / 529, c = e % 529;
        int gy = (y0 - RAD + r) & (PH - 1);
        int gx = (c - RAD) & (PW - 1);
        __half h = __float2half(pb[gy*PW + gx]);
        aEh[r*SAB + c] = h;
        if (c > 0) aOh[r*SAB + c - 1] = h;
    }
    __syncthreads();

    int yl = wid;
    int pe = (lane >> 2) & 1;
    int lofs = ((lane >> 2) >> 1) + (lane & 3);
    const uint32_t* pAbase = pe ? aO : aE;
    int bi0 = (lane & 3)*8 + (lane >> 2);

    for (int xt = 0; xt < 8; xt++) {
        int x0 = xt * 64;
        int xofs = x0 >> 1;
        float acc[4][4];
        #pragma unroll
        for (int mf = 0; mf < 4; mf++)
            acc[mf][0] = acc[mf][1] = acc[mf][2] = acc[mf][3] = 0.f;

        #pragma unroll 1
        for (int i = 0; i < FS; i++) {
            const uint32_t* pA = pAbase + (yl + i)*SAU + xofs + lofs;
            uint32_t va[9];
            #pragma unroll
            for (int s = 0; s < 9; s++) va[s] = pA[4*s];
            uint32_t b0 = Bs[i*64 + bi0];
            uint32_t b1 = Bs[i*64 + bi0 + 32];
            #pragma unroll
            for (int mf = 0; mf < 4; mf++) {
                uint32_t a[4] = {va[2*mf], va[2*mf+1], va[2*mf+1], va[2*mf+2]};
                mma_f16(acc[mf], a, b0, b1);
            }
        }

        int y = y0 + yl;
        int n0 = 2*(lane & 3);
        #pragma unroll
        for (int mf = 0; mf < 4; mf++) {
            int xa = x0 + mf*16 + (lane >> 2);
            #pragma unroll
            for (int q = 0; q < 4; q++) {
                int o = n0 + (q & 1);
                if (o >= NF) continue;
                int x = xa + (q >> 1)*8;
                float v = acc[mf][q];
                size_t off = (((size_t)(b*NF + o))*PH + y)*PW + x;
                codes[off] = v;
                g_h[off] = __float2half(v * FSCALE);
            }
        }
    }
}

// ===========================================================================
// Kernel 3: gram via mma.sync fp16 single-term, 8 warps, warp-tile 64x32,
// 4-stage ring. Uneven 29-way k-split (one wave). Diag pairs skip the 2
// fully-below-diagonal warp blocks.
// ===========================================================================
__device__ __forceinline__ void gram_load_stage(uint32_t sbase, int stage, int kit,
                                                int ti, int tj, int tid, int nm) {
    uint32_t st = sbase + stage * STAGE_BY;
    size_t kbyte = (size_t)kit * (KB * 2);
    #pragma unroll
    for (int s = 0; s < 2; s++) {
        int c = tid + s * 256;            // 0..511
        int row = c >> 2, k8 = c & 3;
        uint32_t doff = (uint32_t)(row * (TSTRIDE*2) + k8 * 16);
        #pragma unroll
        for (int m = 0; m < 2; m++) {
            if (m >= nm) break;
            int grow = ((m == 0) ? ti : tj) * 128 + row;
            uint32_t dst = st + m * TILE_BY + doff;
            const char* src = (const char*)g_h + (size_t)min(grow, N_ROWS-1) * (K_TOT*2) + kbyte + k8 * 16;
            if (grow < N_ROWS) cp16(dst, src);
            else               cp16z(dst, src);
        }
    }
}

__global__ __launch_bounds__(256, 2)
void gram_mma_kernel() {
    extern __shared__ char dsm[];
    uint32_t sbase = smem_u32(dsm);

    int pair = blockIdx.x;
    int ksp  = blockIdx.y;
    int ti = 0, rem = pair, cnt = GT;
    while (rem >= cnt) { rem -= cnt; ti++; cnt--; }
    int tj = ti + rem;
    bool diag = (ti == tj);
    int nm = diag ? 1 : 2;

    int kstart = 35*ksp + min(ksp, 9);
    int kiters = 35 + (ksp < 9 ? 1 : 0);

    int tid  = threadIdx.x;
    int wid  = tid >> 5, lane = tid & 31;
    int warp_m = wid & 1;        // 2 m-tiles of 64 rows
    int warp_n = wid >> 1;       // 4 n-tiles of 32 cols
    bool active = !(diag && warp_m == 1 && warp_n < 2);

    float acc[4][4][4];
    #pragma unroll
    for (int mi = 0; mi < 4; mi++)
        #pragma unroll
        for (int ni = 0; ni < 4; ni++)
            #pragma unroll
            for (int q = 0; q < 4; q++) acc[mi][ni][q] = 0.f;

    uint32_t a_off = (uint32_t)((warp_m*64 + (lane & 15)) * (TSTRIDE*2) + ((lane >> 4) & 1) * 16);
    uint32_t b_off = (uint32_t)((warp_n*32 + (lane & 15)) * (TSTRIDE*2) + ((lane >> 4) & 1) * 16);

    #pragma unroll
    for (int p = 0; p < 3; p++) {
        gram_load_stage(sbase, p, kstart + p, ti, tj, tid, nm);
        cp_commit();
    }

    for (int it = 0; it < kiters; it++) {
        cp_wait2();
        __syncthreads();

        int nx = it + 3;
        if (nx < kiters) gram_load_stage(sbase, nx & 3, kstart + nx, ti, tj, tid, nm);
        cp_commit();

        if (active) {
            uint32_t st = sbase + (it & 3) * STAGE_BY;
            uint32_t aB = st;
            uint32_t bB = diag ? st : st + TILE_BY;

            #pragma unroll
            for (int k16 = 0; k16 < 2; k16++) {
                uint32_t kadd = (uint32_t)(k16 * 32);
                uint32_t af[4][4], bf[2][4];
                #pragma unroll
                for (int mi = 0; mi < 4; mi++)
                    ldm_x4(af[mi], aB + a_off + kadd + mi*16*(TSTRIDE*2));
                #pragma unroll
                for (int n2 = 0; n2 < 2; n2++)
                    ldm_x4(bf[n2], bB + b_off + kadd + n2*16*(TSTRIDE*2));
                #pragma unroll
                for (int mi = 0; mi < 4; mi++)
                    #pragma unroll
                    for (int ni = 0; ni < 4; ni++) {
                        int n2 = ni >> 1, sel = ni & 1;
                        mma_f16(acc[mi][ni], af[mi], bf[n2][sel], bf[n2][sel+2]);
                    }
            }
        }
    }

    if (active) {
        float* dst = &g_gpart[pair][ksp][0];
        int r0 = warp_m * 64;
        int c0 = warp_n * 32;
        #pragma unroll
        for (int mi = 0; mi < 4; mi++) {
            #pragma unroll
            for (int ni = 0; ni < 4; ni++) {
                int row = r0 + mi*16 + (lane >> 2);
                int col = c0 + ni*8 + (lane & 3) * 2;
                *(float2*)&dst[row * 128 + col]       = make_float2(acc[mi][ni][0], acc[mi][ni][1]);
                *(float2*)&dst[(row + 8) * 128 + col] = make_float2(acc[mi][ni][2], acc[mi][ni][3]);
            }
        }
    }
}

// ===========================================================================
// Kernel 4: reduce 29 K-splits, 4 threads per float4 element, deterministic
// fixed-order sums, scale, symmetric write. Diag pairs: only upper-tri
// 32x32 blocks processed; mirrored writes cover the lower half.
// ===========================================================================
__global__ void gram_reduce_kernel(float* __restrict__ gram) {
    __shared__ float4 sm[64][4];
    int bid  = blockIdx.x;            // 0..639
    int pair = bid >> 6;
    int eblk = bid & 63;
    int tid  = threadIdx.x;
    int el   = tid >> 2;              // 0..63
    int q    = tid & 3;

    int e4 = (eblk * 64 + el) * 4;    // float index within 16384
    int ii = e4 >> 7, jj = e4 & 127;

    int ti = 0, rem = pair, cnt = GT;
    while (rem >= cnt) { rem -= cnt; ti++; cnt--; }
    int tj = ti + rem;
    bool diag = (ti == tj);
    if (diag && (ii >> 5) > (jj >> 5)) return;   // mirror covers these

    int kstart = q * 8;
    int kcnt   = (q < 3) ? 8 : 5;     // 8+8+8+5 = 29

    const float* base = &g_gpart[pair][0][0];
    float4 s = make_float4(0.f, 0.f, 0.f, 0.f);
    for (int k = 0; k < kcnt; k++) {
        float4 v = *(const float4*)(base + (size_t)(kstart + k) * 16384 + e4);
        s.x += v.x; s.y += v.y; s.z += v.z; s.w += v.w;
    }
    sm[el][q] = s;
    __syncwarp();

    if (q == 0) {
        float4 a = sm[el][0], b = sm[el][1], c = sm[el][2], d = sm[el][3];
        float vs[4];
        vs[0] = (((a.x + b.x) + c.x) + d.x) * GRAM_SCALE;
        vs[1] = (((a.y + b.y) + c.y) + d.y) * GRAM_SCALE;
        vs[2] = (((a.z + b.z) + c.z) + d.z) * GRAM_SCALE;
        vs[3] = (((a.w + b.w) + c.w) + d.w) * GRAM_SCALE;

        int gi  = ti * 128 + ii;
        int gj0 = tj * 128 + jj;
        if (gi < N_ROWS) {
            #pragma unroll
            for (int p = 0; p < 4; p++) {
                int gj = gj0 + p;
                if (gj >= N_ROWS) continue;
                gram[gi * N_ROWS + gj] = vs[p];
                gram[gj * N_ROWS + gi] = vs[p];
            }
        }
    }
}

// ===========================================================================
extern "C" void kernel_launch(void* const* d_in, const int* in_sizes, int n_in,
                              void* d_out, int out_size) {
    const float* image = (const float*)d_in[0];
    const float* pupil = (const float*)d_in[1];
    const float* iris  = (const float*)d_in[2];
    const float* filt  = (const float*)d_in[3];

    float* out   = (float*)d_out;
    float* codes = out + CODES_OFF;
    float* gram  = out + GRAM_OFF;
    float* polar = out + POLAR_OFF;

    cudaFuncSetAttribute(conv_mma_kernel,
                         cudaFuncAttributeMaxDynamicSharedMemorySize, CONV_SMEM);
    cudaFuncSetAttribute(gram_mma_kernel,
                         cudaFuncAttributeMaxDynamicSharedMemorySize, GSMEM);

    polar_kernel<<<(B * PH * PW) / 256, 256>>>(image, pupil, iris, polar);
    conv_mma_kernel<<<dim3(B, PH/8), 256, CONV_SMEM>>>(polar, filt, codes);
    gram_mma_kernel<<<dim3(GPAIRS, GKSPLIT), 256, GSMEM>>>();
    gram_reduce_kernel<<<GPAIRS * 64, 256>>>(gram);
}

// round 16
// speedup vs baseline: 1.0689x; 1.0689x over previous
#include <cuda_runtime.h>
#include <cuda_fp16.h>
#include <cstdint>

#define B   64
#define H   480
#define W   640
#define PH  64
#define PW  512
#define FS  15
#define NF  7
#define RAD 7

#define K_TOT   (PH*PW)          // 32768
#define N_ROWS  (B*NF)           // 448

#define CODES_OFF 0
#define GRAM_OFF  (B*NF*PH*PW)                // 14680064
#define POLAR_OFF (GRAM_OFF + N_ROWS*N_ROWS)  // 14880768

#define FSCALE      0.0625f                   // feats stored * 1/16
#define GRAM_SCALE  (256.0f / 14680064.0f)    // undo FSCALE^2 and normalize

// ---- gram tiling ----
// KB=64 halves per k-iter; 512 total k-iters split unevenly over 29 CTAs:
// splits 0..18 do 18 iters, 19..28 do 17  (19*18 + 10*17 = 512).
// Grid = 10 x 29 = 290 CTAs = ONE wave at 2 CTAs/SM.
#define GT       4
#define GPAIRS   10
#define GKSPLIT  29
#define KB       64

#define TSTRIDE  72                 // fp16 per smem row (144B, 9x16B -> conflict-free)
#define TILE_BY  (128*TSTRIDE*2)    // 18432 B
#define STAGE_BY (2*TILE_BY)        // 36864 B (A|B)
#define NSTAGE   2
#define GSMEM    (NSTAGE*STAGE_BY)  // 73728 B -> 2 CTAs/SM

// ---- conv (fp16 implicit GEMM, single term) ----
#define SAB 536                     // fp16 stride per A row
#define SAU 268                     // u32 stride
#define AROWS 22                    // 8 + 14
#define ATILE_U32 (AROWS*SAU)       // 5896
#define CONV_SMEM ((2*ATILE_U32 + 960)*4)     // 51008 B -> 4 CTAs/SM

// scratch (device-code references ONLY — host-side symbol use is a silent
// ATS write to host BSS on GB300)
__device__ __half g_h[(size_t)N_ROWS * K_TOT];
__device__ float g_gpart[GPAIRS][GKSPLIT][128*128];

// ===========================================================================
// helpers
// ===========================================================================
__device__ __forceinline__ uint32_t smem_u32(const void* p) {
    uint32_t a;
    asm("{ .reg .u64 t; cvta.to.shared.u64 t, %1; cvt.u32.u64 %0, t; }" : "=r"(a) : "l"(p));
    return a;
}

__device__ __forceinline__ void cp16(uint32_t dst, const void* src) {
    asm volatile("cp.async.ca.shared.global [%0], [%1], 16;" :: "r"(dst), "l"(src));
}
__device__ __forceinline__ void cp16z(uint32_t dst, const void* src) {
    asm volatile("cp.async.ca.shared.global [%0], [%1], 16, 0;" :: "r"(dst), "l"(src));
}
__device__ __forceinline__ void cp_commit() { asm volatile("cp.async.commit_group;" ::: "memory"); }
__device__ __forceinline__ void cp_wait0()  { asm volatile("cp.async.wait_group 0;" ::: "memory"); }

__device__ __forceinline__ void ldm_x4(uint32_t* r, uint32_t addr) {
    asm volatile("ldmatrix.sync.aligned.m8n8.x4.shared.b16 {%0,%1,%2,%3}, [%4];"
        : "=r"(r[0]), "=r"(r[1]), "=r"(r[2]), "=r"(r[3]) : "r"(addr));
}
__device__ __forceinline__ void mma_f16(float* c, const uint32_t* a, uint32_t b0, uint32_t b1) {
    asm volatile("mma.sync.aligned.m16n8k16.row.col.f32.f16.f16.f32 "
        "{%0,%1,%2,%3}, {%4,%5,%6,%7}, {%8,%9}, {%0,%1,%2,%3};"
        : "+f"(c[0]), "+f"(c[1]), "+f"(c[2]), "+f"(c[3])
        : "r"(a[0]), "r"(a[1]), "r"(a[2]), "r"(a[3]), "r"(b0), "r"(b1));
}

// ===========================================================================
// Kernel 1: polar bilinear resample (MUFU sin/cos)
// ===========================================================================
__global__ void polar_kernel(const float* __restrict__ img,
                             const float* __restrict__ pupil,
                             const float* __restrict__ iris,
                             float* __restrict__ polar) {
    int idx = blockIdx.x * blockDim.x + threadIdx.x;
    if (idx >= B * PH * PW) return;
    int col = idx % PW;
    int row = (idx / PW) % PH;
    int b   = idx / (PH * PW);

    float theta = 6.283185307179586f * (float)(col + 1) * (1.0f / (float)PW);
    float ct = __cosf(theta), st = __sinf(theta);

    float pcx = pupil[b*3+0], pcy = pupil[b*3+1], pr = pupil[b*3+2];
    float icx = iris [b*3+0], icy = iris [b*3+1], ir = iris [b*3+2];

    float px = pcx + pr * ct;
    float py = pcy + pr * st;
    float ix = icx + ir * ct;
    float iy = icy + ir * st;

    float rad = (float)row / (float)(PH - 1);
    float xg = (1.0f - rad) * px + rad * ix;
    float yg = (1.0f - rad) * py + rad * iy;

    float x = fminf(fmaxf(xg, 0.0f), (float)(W - 1));
    float y = fminf(fmaxf(yg, 0.0f), (float)(H - 1));

    float xn = x / (float)(W - 1) * 2.0f - 1.0f;
    float yn = y / (float)(H - 1) * 2.0f - 1.0f;
    float gx = ((xn + 1.0f) * 0.5f * (float)W - 0.5f) / (float)(W - 1) * 2.0f - 1.0f;
    float gy = ((yn + 1.0f) * 0.5f * (float)H - 0.5f) / (float)(H - 1) * 2.0f - 1.0f;
    float sx = ((gx + 1.0f) * (float)W - 1.0f) * 0.5f;
    float sy = ((gy + 1.0f) * (float)H - 1.0f) * 0.5f;

    float x0f = floorf(sx), y0f = floorf(sy);
    float wx = sx - x0f, wy = sy - y0f;
    int x0 = (int)x0f, y0 = (int)y0f;

    const float* im = img + (size_t)b * H * W;

    float v00 = 0.f, v01 = 0.f, v10 = 0.f, v11 = 0.f;
    bool xv0 = (x0 >= 0) && (x0 < W);
    bool xv1 = (x0+1 >= 0) && (x0+1 < W);
    bool yv0 = (y0 >= 0) && (y0 < H);
    bool yv1 = (y0+1 >= 0) && (y0+1 < H);
    int x0c = min(max(x0, 0), W-1), x1c = min(max(x0+1, 0), W-1);
    int y0c = min(max(y0, 0), H-1), y1c = min(max(y0+1, 0), H-1);
    if (xv0 && yv0) v00 = im[y0c*W + x0c] * 255.0f;
    if (xv1 && yv0) v01 = im[y0c*W + x1c] * 255.0f;
    if (xv0 && yv1) v10 = im[y1c*W + x0c] * 255.0f;
    if (xv1 && yv1) v11 = im[y1c*W + x1c] * 255.0f;

    float v = v00*(1.0f-wx)*(1.0f-wy) + v01*wx*(1.0f-wy)
            + v10*(1.0f-wx)*wy        + v11*wx*wy;
    polar[idx] = v;
}

// ===========================================================================
// Kernel 2: conv as fp16 implicit GEMM, SINGLE term. (unchanged R10)
// ===========================================================================
__global__ __launch_bounds__(256, 4)
void conv_mma_kernel(const float* __restrict__ polar,
                     const float* __restrict__ filt,
                     float* __restrict__ codes) {
    extern __shared__ uint32_t cs[];
    uint32_t* aE  = cs;
    uint32_t* aO  = cs + ATILE_U32;
    uint32_t* Bs  = cs + 2*ATILE_U32;

    int b  = blockIdx.x;
    int y0 = blockIdx.y * 8;
    int tid = threadIdx.x, wid = tid >> 5, lane = tid & 31;

    for (int e = tid; e < 960; e += 256) {
        int i = e >> 6, kp = (e >> 3) & 7, n = e & 7;
        int k0 = 2*kp, k1 = 2*kp + 1;
        float w0 = (k0 < FS && n < NF) ? filt[(i*FS + k0)*NF + (6 - n)] : 0.f;
        float w1 = (k1 < FS && n < NF) ? filt[(i*FS + k1)*NF + (6 - n)] : 0.f;
        __half h0 = __float2half(w0);
        __half h1 = __float2half(w1);
        Bs[e] = ((uint32_t)__half_as_ushort(h1) << 16) | __half_as_ushort(h0);
    }
    const float* pb = polar + (size_t)b * PH * PW;
    __half* aEh = (__half*)aE;
    __half* aOh = (__half*)aO;
    for (int e = tid; e < AROWS * 529; e += 256) {
        int r = e / 529, c = e % 529;
        int gy = (y0 - RAD + r) & (PH - 1);
        int gx = (c - RAD) & (PW - 1);
        __half h = __float2half(pb[gy*PW + gx]);
        aEh[r*SAB + c] = h;
        if (c > 0) aOh[r*SAB + c - 1] = h;
    }
    __syncthreads();

    int yl = wid;
    int pe = (lane >> 2) & 1;
    int lofs = ((lane >> 2) >> 1) + (lane & 3);
    const uint32_t* pAbase = pe ? aO : aE;
    int bi0 = (lane & 3)*8 + (lane >> 2);

    for (int xt = 0; xt < 8; xt++) {
        int x0 = xt * 64;
        int xofs = x0 >> 1;
        float acc[4][4];
        #pragma unroll
        for (int mf = 0; mf < 4; mf++)
            acc[mf][0] = acc[mf][1] = acc[mf][2] = acc[mf][3] = 0.f;

        #pragma unroll 1
        for (int i = 0; i < FS; i++) {
            const uint32_t* pA = pAbase + (yl + i)*SAU + xofs + lofs;
            uint32_t va[9];
            #pragma unroll
            for (int s = 0; s < 9; s++) va[s] = pA[4*s];
            uint32_t b0 = Bs[i*64 + bi0];
            uint32_t b1 = Bs[i*64 + bi0 + 32];
            #pragma unroll
            for (int mf = 0; mf < 4; mf++) {
                uint32_t a[4] = {va[2*mf], va[2*mf+1], va[2*mf+1], va[2*mf+2]};
                mma_f16(acc[mf], a, b0, b1);
            }
        }

        int y = y0 + yl;
        int n0 = 2*(lane & 3);
        #pragma unroll
        for (int mf = 0; mf < 4; mf++) {
            int xa = x0 + mf*16 + (lane >> 2);
            #pragma unroll
            for (int q = 0; q < 4; q++) {
                int o = n0 + (q & 1);
                if (o >= NF) continue;
                int x = xa + (q >> 1)*8;
                float v = acc[mf][q];
                size_t off = (((size_t)(b*NF + o))*PH + y)*PW + x;
                codes[off] = v;
                g_h[off] = __float2half(v * FSCALE);
            }
        }
    }
}

// ===========================================================================
// Kernel 3: gram via mma.sync fp16 single-term, 8 warps, warp-tile 64x32,
// KB=64 (half the iterations/barriers of KB=32), 2-stage ring, uneven
// 29-way k-split (one wave). Diag pairs skip fully-below-diagonal blocks.
// ===========================================================================
__device__ __forceinline__ void gram_load_stage(uint32_t sbase, int stage, int kit,
                                                int ti, int tj, int tid, int nm) {
    uint32_t st = sbase + stage * STAGE_BY;
    size_t kbyte = (size_t)kit * (KB * 2);     // 128B per row per iter
    #pragma unroll
    for (int s = 0; s < 4; s++) {
        int c = tid + s * 256;            // 0..1023: row = c>>3, 8 chunks of 16B
        int row = c >> 3, k8 = c & 7;
        uint32_t doff = (uint32_t)(row * (TSTRIDE*2) + k8 * 16);
        #pragma unroll
        for (int m = 0; m < 2; m++) {
            if (m >= nm) break;
            int grow = ((m == 0) ? ti : tj) * 128 + row;
            uint32_t dst = st + m * TILE_BY + doff;
            const char* src = (const char*)g_h + (size_t)min(grow, N_ROWS-1) * (K_TOT*2) + kbyte + k8 * 16;
            if (grow < N_ROWS) cp16(dst, src);
            else               cp16z(dst, src);
        }
    }
}

__global__ __launch_bounds__(256, 2)
void gram_mma_kernel() {
    extern __shared__ char dsm[];
    uint32_t sbase = smem_u32(dsm);

    int pair = blockIdx.x;
    int ksp  = blockIdx.y;
    int ti = 0, rem = pair, cnt = GT;
    while (rem >= cnt) { rem -= cnt; ti++; cnt--; }
    int tj = ti + rem;
    bool diag = (ti == tj);
    int nm = diag ? 1 : 2;

    int kstart = 17*ksp + min(ksp, 19);
    int kiters = 17 + (ksp < 19 ? 1 : 0);

    int tid  = threadIdx.x;
    int wid  = tid >> 5, lane = tid & 31;
    int warp_m = wid & 1;        // 2 m-tiles of 64 rows
    int warp_n = wid >> 1;       // 4 n-tiles of 32 cols
    bool active = !(diag && warp_m == 1 && warp_n < 2);

    float acc[4][4][4];
    #pragma unroll
    for (int mi = 0; mi < 4; mi++)
        #pragma unroll
        for (int ni = 0; ni < 4; ni++)
            #pragma unroll
            for (int q = 0; q < 4; q++) acc[mi][ni][q] = 0.f;

    uint32_t a_off = (uint32_t)((warp_m*64 + (lane & 15)) * (TSTRIDE*2) + ((lane >> 4) & 1) * 16);
    uint32_t b_off = (uint32_t)((warp_n*32 + (lane & 15)) * (TSTRIDE*2) + ((lane >> 4) & 1) * 16);

    // prologue: stage 0 in flight
    gram_load_stage(sbase, 0, kstart, ti, tj, tid, nm);
    cp_commit();

    for (int it = 0; it < kiters; it++) {
        cp_wait0();               // load(it) complete
        __syncthreads();          // all warps done with buffer (it+1)&1

        int nx = it + 1;
        if (nx < kiters) gram_load_stage(sbase, nx & 1, kstart + nx, ti, tj, tid, nm);
        cp_commit();

        if (active) {
            uint32_t st = sbase + (it & 1) * STAGE_BY;
            uint32_t aB = st;
            uint32_t bB = diag ? st : st + TILE_BY;

            #pragma unroll
            for (int k16 = 0; k16 < 4; k16++) {
                uint32_t kadd = (uint32_t)(k16 * 32);
                uint32_t af[4][4], bf[2][4];
                #pragma unroll
                for (int mi = 0; mi < 4; mi++)
                    ldm_x4(af[mi], aB + a_off + kadd + mi*16*(TSTRIDE*2));
                #pragma unroll
                for (int n2 = 0; n2 < 2; n2++)
                    ldm_x4(bf[n2], bB + b_off + kadd + n2*16*(TSTRIDE*2));
                #pragma unroll
                for (int mi = 0; mi < 4; mi++)
                    #pragma unroll
                    for (int ni = 0; ni < 4; ni++) {
                        int n2 = ni >> 1, sel = ni & 1;
                        mma_f16(acc[mi][ni], af[mi], bf[n2][sel], bf[n2][sel+2]);
                    }
            }
        }
    }

    if (active) {
        float* dst = &g_gpart[pair][ksp][0];
        int r0 = warp_m * 64;
        int c0 = warp_n * 32;
        #pragma unroll
        for (int mi = 0; mi < 4; mi++) {
            #pragma unroll
            for (int ni = 0; ni < 4; ni++) {
                int row = r0 + mi*16 + (lane >> 2);
                int col = c0 + ni*8 + (lane & 3) * 2;
                *(float2*)&dst[row * 128 + col]       = make_float2(acc[mi][ni][0], acc[mi][ni][1]);
                *(float2*)&dst[(row + 8) * 128 + col] = make_float2(acc[mi][ni][2], acc[mi][ni][3]);
            }
        }
    }
}

// ===========================================================================
// Kernel 4: reduce 29 K-splits, 2 threads per float4 element (MLP ~15 per
// thread), deterministic fixed-order sums, scale, symmetric write.
// Diag pairs: only upper-tri 32x32 blocks; mirrored writes cover the rest.
// ===========================================================================
__global__ void gram_reduce_kernel(float* __restrict__ gram) {
    __shared__ float4 sm[128][2];
    int bid  = blockIdx.x;            // 0..319
    int pair = bid >> 5;
    int eblk = bid & 31;
    int tid  = threadIdx.x;
    int el   = tid >> 1;              // 0..127
    int q    = tid & 1;

    int e4 = (eblk * 128 + el) * 4;   // float index within 16384
    int ii = e4 >> 7, jj = e4 & 127;

    int ti = 0, rem = pair, cnt = GT;
    while (rem >= cnt) { rem -= cnt; ti++; cnt--; }
    int tj = ti + rem;
    bool diag = (ti == tj);
    bool skip = diag && (ii >> 5) > (jj >> 5);   // mirror covers these

    if (!skip) {
        int kstart = q * 15;
        int kcnt   = q ? 14 : 15;     // 15+14 = 29

        const float* base = &g_gpart[pair][0][0];
        float4 s = make_float4(0.f, 0.f, 0.f, 0.f);
        for (int k = 0; k < kcnt; k++) {
            float4 v = *(const float4*)(base + (size_t)(kstart + k) * 16384 + e4);
            s.x += v.x; s.y += v.y; s.z += v.z; s.w += v.w;
        }
        sm[el][q] = s;
    }
    __syncwarp();

    if (q == 0 && !skip) {
        float4 a = sm[el][0], b = sm[el][1];
        float vs[4];
        vs[0] = (a.x + b.x) * GRAM_SCALE;
        vs[1] = (a.y + b.y) * GRAM_SCALE;
        vs[2] = (a.z + b.z) * GRAM_SCALE;
        vs[3] = (a.w + b.w) * GRAM_SCALE;

        int gi  = ti * 128 + ii;
        int gj0 = tj * 128 + jj;
        if (gi < N_ROWS) {
            #pragma unroll
            for (int p = 0; p < 4; p++) {
                int gj = gj0 + p;
                if (gj >= N_ROWS) continue;
                gram[gi * N_ROWS + gj] = vs[p];
                gram[gj * N_ROWS + gi] = vs[p];
            }
        }
    }
}

// ===========================================================================
extern "C" void kernel_launch(void* const* d_in, const int* in_sizes, int n_in,
                              void* d_out, int out_size) {
    const float* image = (const float*)d_in[0];
    const float* pupil = (const float*)d_in[1];
    const float* iris  = (const float*)d_in[2];
    const float* filt  = (const float*)d_in[3];

    float* out   = (float*)d_out;
    float* codes = out + CODES_OFF;
    float* gram  = out + GRAM_OFF;
    float* polar = out + POLAR_OFF;

    cudaFuncSetAttribute(conv_mma_kernel,
                         cudaFuncAttributeMaxDynamicSharedMemorySize, CONV_SMEM);
    cudaFuncSetAttribute(gram_mma_kernel,
                         cudaFuncAttributeMaxDynamicSharedMemorySize, GSMEM);

    polar_kernel<<<(B * PH * PW) / 256, 256>>>(image, pupil, iris, polar);
    conv_mma_kernel<<<dim3(B, PH/8), 256, CONV_SMEM>>>(polar, filt, codes);
    gram_mma_kernel<<<dim3(GPAIRS, GKSPLIT), 256, GSMEM>>>();
    gram_reduce_kernel<<<GPAIRS * 32, 256>>>(gram);
}